// round 2
// baseline (speedup 1.0000x reference)
#include <cuda_runtime.h>
#include <math.h>

#define SEQ   512
#define BATCH 64
#define EMB   300
#define HID   512
#define GATES 2048   // 4*HID
#define NTAG  12
#define NEGV  (-10000.0f)
#define START_TAG 10
#define STOP_TAG  11

// ---------------- scratch (device globals; no allocation) ----------------
__device__ float g_xw[2][SEQ][GATES][BATCH];   // 512 MB: pre-activations x@W_ih.T+b, [dir][scan-step][gate-col][b]
__device__ float g_hf[SEQ][HID][BATCH];        // 64 MB forward hidden states [s][u][b]
__device__ float g_hb[SEQ][HID][BATCH];        // 64 MB backward hidden states in SCAN order
__device__ float g_c[2][HID][BATCH];           // cell state (re-init each launch)
__device__ float g_hinit[2][HID][BATCH];       // transposed h0
__device__ float g_Wt_ih[2][EMB][GATES];       // W_ih transposed [e][j]
__device__ float g_Wt_hh[2][HID][GATES];       // W_hh transposed [k][j]
__device__ float g_feats[SEQ][BATCH][NTAG];

// ---------------- prep: transposes + state init ----------------
__global__ void prep_kernel(const float* Wif, const float* Whf,
                            const float* Wib, const float* Whb,
                            const float* h0, const float* c0) {
    const int N_IH = 2 * EMB * GATES;
    const int N_HH = 2 * HID * GATES;
    const int N_HC = 2 * HID * BATCH;
    const int total = N_IH + N_HH + N_HC;
    for (int idx = blockIdx.x * blockDim.x + threadIdx.x; idx < total;
         idx += gridDim.x * blockDim.x) {
        int i = idx;
        if (i < N_IH) {
            int d = i / (EMB * GATES);
            int r = i % (EMB * GATES);
            int e = r / GATES, j = r % GATES;
            const float* W = d ? Wib : Wif;
            g_Wt_ih[d][e][j] = W[j * EMB + e];
            continue;
        }
        i -= N_IH;
        if (i < N_HH) {
            int d = i / (HID * GATES);
            int r = i % (HID * GATES);
            int k = r / GATES, j = r % GATES;
            const float* W = d ? Whb : Whf;
            g_Wt_hh[d][k][j] = W[j * HID + k];
            continue;
        }
        i -= N_HH;
        {
            int d = i / (HID * BATCH);
            int r = i % (HID * BATCH);
            int u = r / BATCH, b = r % BATCH;
            g_hinit[d][u][b] = h0[(d * BATCH + b) * HID + u];
            g_c[d][u][b]     = c0[(d * BATCH + b) * HID + u];
        }
    }
}

// ---------------- input GEMM: g_xw[dir][s][j][b] = emb(tok) . W_ih[j] + bias ----------------
// One block = one s (64 batch rows) x 64 gate columns. Tiled 64x64, BK=16, 256 thr, 4x4 micro.
__global__ void xw_gemm(const int* __restrict__ tokens,
                        const float* __restrict__ W_emb,
                        const float* __restrict__ b_f,
                        const float* __restrict__ b_b) {
    int dir = blockIdx.z;
    int s   = blockIdx.y;
    int n0  = blockIdx.x * 64;
    __shared__ float As[16][64];
    __shared__ float Bs[16][64];
    __shared__ int   tokS[64];
    int tid = threadIdx.x;
    if (tid < 64) {
        int srow = dir ? (SEQ - 1 - s) : s;
        tokS[tid] = tokens[tid * SEQ + srow];
    }
    __syncthreads();
    int tx = tid & 15, ty = tid >> 4;
    float acc[4][4] = {};
    for (int k0 = 0; k0 < EMB; k0 += 16) {
        for (int l = tid; l < 1024; l += 256) {
            int kk = l >> 6, i = l & 63;
            int k = k0 + kk;
            float a = 0.f, w = 0.f;
            if (k < EMB) {
                a = W_emb[(size_t)tokS[i] * EMB + k];
                w = g_Wt_ih[dir][k][n0 + i];
            }
            As[kk][i] = a;
            Bs[kk][i] = w;
        }
        __syncthreads();
#pragma unroll
        for (int kk = 0; kk < 16; kk++) {
            float4 av = *(const float4*)&As[kk][tx * 4];
            float4 wv = *(const float4*)&Bs[kk][ty * 4];
            float aa[4] = {av.x, av.y, av.z, av.w};
            float ww[4] = {wv.x, wv.y, wv.z, wv.w};
#pragma unroll
            for (int jp = 0; jp < 4; jp++)
#pragma unroll
                for (int bp = 0; bp < 4; bp++)
                    acc[jp][bp] += ww[jp] * aa[bp];
        }
        __syncthreads();
    }
    const float* bias = dir ? b_b : b_f;
#pragma unroll
    for (int jp = 0; jp < 4; jp++) {
        int j = n0 + ty * 4 + jp;
        float bv = bias[j];
        float4 o;
        o.x = acc[jp][0] + bv;
        o.y = acc[jp][1] + bv;
        o.z = acc[jp][2] + bv;
        o.w = acc[jp][3] + bv;
        *(float4*)&g_xw[dir][s][j][tx * 4] = o;
    }
}

// ---------------- fused recurrent step: GEMM(h@W_hh.T) + gates + c/h update ----------------
// Block = 16 hidden units x 4 gates (= 64 gate columns) x all 64 batch. grid (32, 2 dirs).
__global__ void lstm_step(int s) {
    int dir = blockIdx.y;
    int u0  = blockIdx.x * 16;
    const float* hprev = (s == 0) ? &g_hinit[dir][0][0]
                                  : (dir ? &g_hb[s - 1][0][0] : &g_hf[s - 1][0][0]);
    float* hout = dir ? &g_hb[s][0][0] : &g_hf[s][0][0];
    const float* xw = &g_xw[dir][s][0][0];

    __shared__ float As[16][64];
    __shared__ float Bs[16][64];
    __shared__ float Gs[64][68];
    int tid = threadIdx.x, tx = tid & 15, ty = tid >> 4;
    float acc[4][4] = {};
    for (int k0 = 0; k0 < HID; k0 += 16) {
        for (int l = tid; l < 1024; l += 256) {
            int kk = l >> 6, i = l & 63;
            As[kk][i] = hprev[(k0 + kk) * BATCH + i];
            int gate = i >> 4, u = i & 15;
            Bs[kk][i] = g_Wt_hh[dir][k0 + kk][gate * HID + u0 + u];
        }
        __syncthreads();
#pragma unroll
        for (int kk = 0; kk < 16; kk++) {
            float4 av = *(const float4*)&As[kk][tx * 4];
            float4 wv = *(const float4*)&Bs[kk][ty * 4];
            float aa[4] = {av.x, av.y, av.z, av.w};
            float ww[4] = {wv.x, wv.y, wv.z, wv.w};
#pragma unroll
            for (int jp = 0; jp < 4; jp++)
#pragma unroll
                for (int bp = 0; bp < 4; bp++)
                    acc[jp][bp] += ww[jp] * aa[bp];
        }
        __syncthreads();
    }
    // add precomputed xW and park in shared for gate exchange
#pragma unroll
    for (int tp = 0; tp < 4; tp++) {
        int t = ty * 4 + tp;
        int gate = t >> 4, u = t & 15;
        int j = gate * HID + u0 + u;
        float4 x4 = *(const float4*)&xw[j * BATCH + tx * 4];
        Gs[t][tx * 4 + 0] = acc[tp][0] + x4.x;
        Gs[t][tx * 4 + 1] = acc[tp][1] + x4.y;
        Gs[t][tx * 4 + 2] = acc[tp][2] + x4.z;
        Gs[t][tx * 4 + 3] = acc[tp][3] + x4.w;
    }
    __syncthreads();
    // pointwise: 16 hidden units x 64 batch = 1024 elems
    for (int p = tid; p < 1024; p += 256) {
        int u = p >> 6, b = p & 63;
        float gi = Gs[u][b];
        float gf = Gs[16 + u][b];
        float gg = Gs[32 + u][b];
        float go = Gs[48 + u][b];
        float iv = 1.f / (1.f + __expf(-gi));
        float fv = 1.f / (1.f + __expf(-gf));
        float ov = 1.f / (1.f + __expf(-go));
        float c  = fv * g_c[dir][u0 + u][b] + iv * tanhf(gg);
        g_c[dir][u0 + u][b] = c;
        hout[(u0 + u) * BATCH + b] = ov * tanhf(c);
    }
}

// ---------------- feats: [S,B,T] = concat(hf, hb_rev) @ W_out.T + b_out ----------------
__global__ void feats_kernel(const float* __restrict__ W_out,
                             const float* __restrict__ b_out) {
    int s = blockIdx.x;
    int tid = threadIdx.x;            // 768 threads = 64 b x 12 t
    int b = tid / NTAG, t = tid % NTAG;
    __shared__ float hfS[64][64];
    __shared__ float hbS[64][64];
    const float* hfbase = &g_hf[s][0][0];
    const float* hbbase = &g_hb[SEQ - 1 - s][0][0];   // undo reversal
    float acc = b_out[t];
    for (int uc = 0; uc < HID; uc += 64) {
        for (int l = tid; l < 4096; l += 768) {
            int uu = l >> 6, bb = l & 63;
            hfS[uu][bb] = hfbase[(uc + uu) * BATCH + bb];
            hbS[uu][bb] = hbbase[(uc + uu) * BATCH + bb];
        }
        __syncthreads();
#pragma unroll 8
        for (int uu = 0; uu < 64; uu++) {
            acc += hfS[uu][b] * W_out[t * (2 * HID) + uc + uu]
                 + hbS[uu][b] * W_out[t * (2 * HID) + HID + uc + uu];
        }
        __syncthreads();
    }
    g_feats[s][b][t] = acc;
}

// ---------------- CRF forward (single block, sequential over S) ----------------
__global__ void crf_kernel(const int* __restrict__ lengths,
                           const float* __restrict__ trans,
                           float* __restrict__ out) {
    __shared__ float alpha[BATCH][NTAG];
    __shared__ float tr[NTAG][NTAG];
    __shared__ float termS[BATCH][NTAG];
    __shared__ float res[BATCH];
    int tid = threadIdx.x;            // 768 = 64*12
    int b = tid / NTAG, t = tid % NTAG;
    if (tid < NTAG * NTAG) tr[tid / NTAG][tid % NTAG] = trans[tid];
    alpha[b][t] = (t == START_TAG) ? 0.f : NEGV;
    int len = lengths[b];
    __syncthreads();
    for (int s = 0; s < SEQ; s++) {
        float feat = g_feats[s][b][t];
        float v[NTAG];
        float mx = -1e30f;
#pragma unroll
        for (int p = 0; p < NTAG; p++) {
            v[p] = alpha[b][p] + tr[t][p];
            mx = fmaxf(mx, v[p]);
        }
        float sum = 0.f;
#pragma unroll
        for (int p = 0; p < NTAG; p++) sum += __expf(v[p] - mx);
        float newv = mx + __logf(sum) + feat;
        float keep = alpha[b][t];
        float nv = (s < len) ? newv : keep;
        __syncthreads();
        alpha[b][t] = nv;
        __syncthreads();
    }
    termS[b][t] = alpha[b][t] + tr[STOP_TAG][t];
    __syncthreads();
    if (t == 0) {
        float mx = -1e30f;
#pragma unroll
        for (int p = 0; p < NTAG; p++) mx = fmaxf(mx, termS[b][p]);
        float sum = 0.f;
#pragma unroll
        for (int p = 0; p < NTAG; p++) sum += __expf(termS[b][p] - mx);
        res[b] = mx + __logf(sum);
    }
    __syncthreads();
    if (tid == 0) {
        float s2 = 0.f;
        for (int i = 0; i < BATCH; i++) s2 += res[i];
        out[0] = s2 / (float)BATCH;
    }
}

// ---------------- launch ----------------
extern "C" void kernel_launch(void* const* d_in, const int* in_sizes, int n_in,
                              void* d_out, int out_size) {
    const int*   tokens  = (const int*)  d_in[0];
    const int*   lengths = (const int*)  d_in[1];
    const float* W_emb   = (const float*)d_in[2];
    const float* W_ih_f  = (const float*)d_in[3];
    const float* W_hh_f  = (const float*)d_in[4];
    const float* b_f     = (const float*)d_in[5];
    const float* W_ih_b  = (const float*)d_in[6];
    const float* W_hh_b  = (const float*)d_in[7];
    const float* b_b     = (const float*)d_in[8];
    const float* h0      = (const float*)d_in[9];
    const float* c0      = (const float*)d_in[10];
    const float* W_out   = (const float*)d_in[11];
    const float* b_out   = (const float*)d_in[12];
    const float* trans   = (const float*)d_in[13];
    float* out = (float*)d_out;

    prep_kernel<<<2048, 256>>>(W_ih_f, W_hh_f, W_ih_b, W_hh_b, h0, c0);
    xw_gemm<<<dim3(GATES / 64, SEQ, 2), 256>>>(tokens, W_emb, b_f, b_b);
    for (int s = 0; s < SEQ; s++)
        lstm_step<<<dim3(HID / 16, 2), 256>>>(s);
    feats_kernel<<<SEQ, 768>>>(W_out, b_out);
    crf_kernel<<<1, 768>>>(lengths, trans, out);
}

// round 3
// speedup vs baseline: 2.5730x; 2.5730x over previous
#include <cuda_runtime.h>
#include <math.h>

#define SEQ   512
#define BATCH 64
#define EMB   300
#define HID   512
#define GATES 2048   // 4*HID
#define NTAG  12
#define NEGV  (-10000.0f)
#define START_TAG 10
#define STOP_TAG  11
#define NBLK  128

// ---------------- scratch (device globals; no allocation) ----------------
__device__ float g_xw[2][SEQ][GATES][BATCH];   // pre-activations x@W_ih.T+b, [dir][scan-step][gate-col][b]
__device__ float g_hf[SEQ][HID][BATCH];        // forward hidden states [s][u][b]
__device__ float g_hb[SEQ][HID][BATCH];        // backward hidden states in SCAN order
__device__ float g_hinit[2][HID][BATCH];       // transposed h0
__device__ float g_Wt_ih[2][EMB][GATES];       // W_ih transposed [e][j]
__device__ float g_feats[SEQ][BATCH][NTAG];
__device__ unsigned g_cnt = 0;
__device__ volatile unsigned g_gen = 0;

// ---------------- f32x2 helpers ----------------
__device__ __forceinline__ unsigned long long splat2(float x) {
    unsigned long long r; unsigned u = __float_as_uint(x);
    asm("mov.b64 %0, {%1, %1};" : "=l"(r) : "r"(u));
    return r;
}
__device__ __forceinline__ void ffma2(unsigned long long& d,
                                      unsigned long long a,
                                      unsigned long long b) {
    asm("fma.rn.f32x2 %0, %1, %2, %0;" : "+l"(d) : "l"(a), "l"(b));
}
__device__ __forceinline__ float2 unpack2(unsigned long long v) {
    unsigned lo, hi;
    asm("mov.b64 {%0, %1}, %2;" : "=r"(lo), "=r"(hi) : "l"(v));
    float2 f; f.x = __uint_as_float(lo); f.y = __uint_as_float(hi);
    return f;
}
__device__ __forceinline__ float sigf(float x) { return 1.f / (1.f + __expf(-x)); }
__device__ __forceinline__ float tanhfast(float x) { return 2.f / (1.f + __expf(-2.f * x)) - 1.f; }

// ---------------- prep: W_ih transpose + h0 transpose ----------------
__global__ void prep_kernel(const float* Wif, const float* Wib, const float* h0) {
    const int N_IH = 2 * EMB * GATES;
    const int N_H  = 2 * HID * BATCH;
    const int total = N_IH + N_H;
    for (int idx = blockIdx.x * blockDim.x + threadIdx.x; idx < total;
         idx += gridDim.x * blockDim.x) {
        int i = idx;
        if (i < N_IH) {
            int d = i / (EMB * GATES);
            int r = i % (EMB * GATES);
            int e = r / GATES, j = r % GATES;
            const float* W = d ? Wib : Wif;
            g_Wt_ih[d][e][j] = W[j * EMB + e];
        } else {
            i -= N_IH;
            int d = i / (HID * BATCH);
            int r = i % (HID * BATCH);
            int u = r / BATCH, b = r % BATCH;
            g_hinit[d][u][b] = h0[(d * BATCH + b) * HID + u];
        }
    }
}

// ---------------- input GEMM: g_xw[dir][s][j][b] = emb(tok) . W_ih[j] + bias ----------------
__global__ void xw_gemm(const int* __restrict__ tokens,
                        const float* __restrict__ W_emb,
                        const float* __restrict__ b_f,
                        const float* __restrict__ b_b) {
    int dir = blockIdx.z;
    int s   = blockIdx.y;
    int n0  = blockIdx.x * 64;
    __shared__ float As[16][64];
    __shared__ float Bs[16][64];
    __shared__ int   tokS[64];
    int tid = threadIdx.x;
    if (tid < 64) {
        int srow = dir ? (SEQ - 1 - s) : s;
        tokS[tid] = tokens[tid * SEQ + srow];
    }
    __syncthreads();
    int tx = tid & 15, ty = tid >> 4;
    float acc[4][4] = {};
    for (int k0 = 0; k0 < EMB; k0 += 16) {
        for (int l = tid; l < 1024; l += 256) {
            int kk = l >> 6, i = l & 63;
            int k = k0 + kk;
            float a = 0.f, w = 0.f;
            if (k < EMB) {
                a = W_emb[(size_t)tokS[i] * EMB + k];
                w = g_Wt_ih[dir][k][n0 + i];
            }
            As[kk][i] = a;
            Bs[kk][i] = w;
        }
        __syncthreads();
#pragma unroll
        for (int kk = 0; kk < 16; kk++) {
            float4 av = *(const float4*)&As[kk][tx * 4];
            float4 wv = *(const float4*)&Bs[kk][ty * 4];
            float aa[4] = {av.x, av.y, av.z, av.w};
            float ww[4] = {wv.x, wv.y, wv.z, wv.w};
#pragma unroll
            for (int jp = 0; jp < 4; jp++)
#pragma unroll
                for (int bp = 0; bp < 4; bp++)
                    acc[jp][bp] += ww[jp] * aa[bp];
        }
        __syncthreads();
    }
    const float* bias = dir ? b_b : b_f;
#pragma unroll
    for (int jp = 0; jp < 4; jp++) {
        int j = n0 + ty * 4 + jp;
        float bv = bias[j];
        float4 o;
        o.x = acc[jp][0] + bv;
        o.y = acc[jp][1] + bv;
        o.z = acc[jp][2] + bv;
        o.w = acc[jp][3] + bv;
        *(float4*)&g_xw[dir][s][j][tx * 4] = o;
    }
}

// ---------------- persistent fused BiLSTM: 512 steps, grid-wide barrier ----------------
// 128 blocks x 256 thr. Block = dir + 8 hidden units (32 gate cols) x 64 batch.
// W slice staged in shared once (col-pair layout, stride 513 -> conflict-free LDS.64).
// Inner product in packed f32x2; cell state in registers.
__global__ __launch_bounds__(256, 1)
void lstm_persistent(const float* __restrict__ Whf, const float* __restrict__ Whb,
                     const float* __restrict__ c0in) {
    extern __shared__ float smem[];
    float2* sW = (float2*)smem;                // [16 col-pairs][513 k]
    float*  sH = smem + 16 * 513 * 2;          // two 64x64 h chunks (8192 floats)
    float*  sG = sH;                           // gate exchange aliases buffer 0
    __shared__ unsigned sgen;

    int tid = threadIdx.x;
    int bid = blockIdx.x;
    int dir = bid >> 6;
    int u0  = (bid & 63) * 8;
    const float* Whh = dir ? Whb : Whf;

    if (tid == 0) sgen = g_gen;

    // stage W pairs: sW[cp][k] = (W[j(2cp)][k], W[j(2cp+1)][k])
    for (int l = tid; l < 16 * 512; l += 256) {
        int cp = l >> 9, k = l & 511;
        int ca = cp * 2, cb = ca + 1;
        int ja = (ca >> 3) * HID + u0 + (ca & 7);
        int jb = (cb >> 3) * HID + u0 + (cb & 7);
        float2 v;
        v.x = Whh[ja * HID + k];
        v.y = Whh[jb * HID + k];
        sW[cp * 513 + k] = v;
    }

    int cp  = (tid >> 3) & 15;                 // col-pair 0..15
    int c0i = cp * 2;
    int b0  = (tid & 7) * 4 + (tid >> 7) * 32; // batch base (warp spans 32 batch)

    // cell state in registers
    float cst[2];
#pragma unroll
    for (int idx = 0; idx < 2; idx++) {
        int p = tid + 256 * idx;
        int uu = p >> 6, b = p & 63;
        cst[idx] = c0in[(dir * BATCH + b) * HID + (u0 + uu)];
    }
    __syncthreads();

    const float2* wrow = sW + cp * 513;

    for (int s = 0; s < SEQ; s++) {
        const float* hprev = (s == 0) ? &g_hinit[dir][0][0]
                                      : (dir ? &g_hb[s - 1][0][0] : &g_hf[s - 1][0][0]);
        // preload chunk 0
#pragma unroll
        for (int r = 0; r < 4; r++) {
            int m = tid + 256 * r;
            float4 v = *(const float4*)(hprev + (m >> 4) * BATCH + (m & 15) * 4);
            *(float4*)(sH + (m >> 4) * BATCH + (m & 15) * 4) = v;
        }
        __syncthreads();

        unsigned long long a00 = 0, a01 = 0, a10 = 0, a11 = 0;
        int buf = 0;
#pragma unroll 1
        for (int ch = 0; ch < 8; ch++) {
            float4 pf[4];
            if (ch < 7) {
#pragma unroll
                for (int r = 0; r < 4; r++) {
                    int m = tid + 256 * r;
                    pf[r] = *(const float4*)(hprev + ((ch + 1) * 64 + (m >> 4)) * BATCH + (m & 15) * 4);
                }
            }
            const float* hb_ = sH + buf * 4096;
            int k0 = ch * 64;
#pragma unroll 8
            for (int kk = 0; kk < 64; kk += 2) {
                float2 wA = wrow[k0 + kk];
                float2 wB = wrow[k0 + kk + 1];
                ulonglong2 hA = *(const ulonglong2*)(hb_ + kk * BATCH + b0);
                ulonglong2 hB = *(const ulonglong2*)(hb_ + (kk + 1) * BATCH + b0);
                unsigned long long wa0 = splat2(wA.x), wa1 = splat2(wA.y);
                unsigned long long wb0 = splat2(wB.x), wb1 = splat2(wB.y);
                ffma2(a00, hA.x, wa0); ffma2(a01, hA.y, wa0);
                ffma2(a10, hA.x, wa1); ffma2(a11, hA.y, wa1);
                ffma2(a00, hB.x, wb0); ffma2(a01, hB.y, wb0);
                ffma2(a10, hB.x, wb1); ffma2(a11, hB.y, wb1);
            }
            if (ch < 7) {
#pragma unroll
                for (int r = 0; r < 4; r++) {
                    int m = tid + 256 * r;
                    *(float4*)(sH + (buf ^ 1) * 4096 + (m >> 4) * BATCH + (m & 15) * 4) = pf[r];
                }
            }
            __syncthreads();
            buf ^= 1;
        }

        // gates: add xw, park in shared
        {
            int g0 = c0i >> 3, uu0 = c0i & 7;
            int j0 = g0 * HID + u0 + uu0;
            int c1i = c0i + 1;
            int g1 = c1i >> 3, uu1 = c1i & 7;
            int j1 = g1 * HID + u0 + uu1;
            float4 x0 = *(const float4*)&g_xw[dir][s][j0][b0];
            float4 x1 = *(const float4*)&g_xw[dir][s][j1][b0];
            float2 v00 = unpack2(a00), v01 = unpack2(a01);
            float2 v10 = unpack2(a10), v11 = unpack2(a11);
            float4 o0 = {v00.x + x0.x, v00.y + x0.y, v01.x + x0.z, v01.y + x0.w};
            float4 o1 = {v10.x + x1.x, v10.y + x1.y, v11.x + x1.z, v11.y + x1.w};
            *(float4*)(sG + c0i * 68 + b0) = o0;
            *(float4*)(sG + c1i * 68 + b0) = o1;
        }
        __syncthreads();

        // pointwise: 8 units x 64 batch, 2 per thread; c stays in registers
        float* hout = dir ? &g_hb[s][0][0] : &g_hf[s][0][0];
#pragma unroll
        for (int idx = 0; idx < 2; idx++) {
            int p = tid + 256 * idx;
            int uu = p >> 6, b = p & 63;
            float gi = sG[uu * 68 + b];
            float gf = sG[(8 + uu) * 68 + b];
            float gg = sG[(16 + uu) * 68 + b];
            float go = sG[(24 + uu) * 68 + b];
            float iv = sigf(gi), fv = sigf(gf), ov = sigf(go);
            float c = fv * cst[idx] + iv * tanhfast(gg);
            cst[idx] = c;
            hout[(u0 + uu) * BATCH + b] = ov * tanhfast(c);
        }

        // grid-wide barrier
        __syncthreads();
        if (tid == 0) {
            unsigned target = sgen + 1;
            __threadfence();
            unsigned a = atomicAdd(&g_cnt, 1);
            if (a == NBLK - 1) {
                g_cnt = 0;
                __threadfence();
                g_gen = target;
            } else {
                while (g_gen != target) { }
            }
            sgen = target;
        }
        __syncthreads();
    }
}

// ---------------- feats: [S,B,T] = concat(hf, hb_rev) @ W_out.T + b_out ----------------
__global__ void feats_kernel(const float* __restrict__ W_out,
                             const float* __restrict__ b_out) {
    int s = blockIdx.x;
    int tid = threadIdx.x;            // 768 threads = 64 b x 12 t
    int b = tid / NTAG, t = tid % NTAG;
    __shared__ float hfS[64][64];
    __shared__ float hbS[64][64];
    const float* hfbase = &g_hf[s][0][0];
    const float* hbbase = &g_hb[SEQ - 1 - s][0][0];   // undo reversal
    float acc = b_out[t];
    for (int uc = 0; uc < HID; uc += 64) {
        for (int l = tid; l < 4096; l += 768) {
            int uu = l >> 6, bb = l & 63;
            hfS[uu][bb] = hfbase[(uc + uu) * BATCH + bb];
            hbS[uu][bb] = hbbase[(uc + uu) * BATCH + bb];
        }
        __syncthreads();
#pragma unroll 8
        for (int uu = 0; uu < 64; uu++) {
            acc += hfS[uu][b] * W_out[t * (2 * HID) + uc + uu]
                 + hbS[uu][b] * W_out[t * (2 * HID) + HID + uc + uu];
        }
        __syncthreads();
    }
    g_feats[s][b][t] = acc;
}

// ---------------- CRF forward (single block, sequential over S) ----------------
__global__ void crf_kernel(const int* __restrict__ lengths,
                           const float* __restrict__ trans,
                           float* __restrict__ out) {
    __shared__ float alpha[BATCH][NTAG];
    __shared__ float tr[NTAG][NTAG];
    __shared__ float termS[BATCH][NTAG];
    __shared__ float res[BATCH];
    int tid = threadIdx.x;            // 768 = 64*12
    int b = tid / NTAG, t = tid % NTAG;
    if (tid < NTAG * NTAG) tr[tid / NTAG][tid % NTAG] = trans[tid];
    alpha[b][t] = (t == START_TAG) ? 0.f : NEGV;
    int len = lengths[b];
    __syncthreads();
    for (int s = 0; s < SEQ; s++) {
        float feat = g_feats[s][b][t];
        float v[NTAG];
        float mx = -1e30f;
#pragma unroll
        for (int p = 0; p < NTAG; p++) {
            v[p] = alpha[b][p] + tr[t][p];
            mx = fmaxf(mx, v[p]);
        }
        float sum = 0.f;
#pragma unroll
        for (int p = 0; p < NTAG; p++) sum += __expf(v[p] - mx);
        float newv = mx + __logf(sum) + feat;
        float keep = alpha[b][t];
        float nv = (s < len) ? newv : keep;
        __syncthreads();
        alpha[b][t] = nv;
        __syncthreads();
    }
    termS[b][t] = alpha[b][t] + tr[STOP_TAG][t];
    __syncthreads();
    if (t == 0) {
        float mx = -1e30f;
#pragma unroll
        for (int p = 0; p < NTAG; p++) mx = fmaxf(mx, termS[b][p]);
        float sum = 0.f;
#pragma unroll
        for (int p = 0; p < NTAG; p++) sum += __expf(termS[b][p] - mx);
        res[b] = mx + __logf(sum);
    }
    __syncthreads();
    if (tid == 0) {
        float s2 = 0.f;
        for (int i = 0; i < BATCH; i++) s2 += res[i];
        out[0] = s2 / (float)BATCH;
    }
}

// ---------------- launch ----------------
extern "C" void kernel_launch(void* const* d_in, const int* in_sizes, int n_in,
                              void* d_out, int out_size) {
    const int*   tokens  = (const int*)  d_in[0];
    const int*   lengths = (const int*)  d_in[1];
    const float* W_emb   = (const float*)d_in[2];
    const float* W_ih_f  = (const float*)d_in[3];
    const float* W_hh_f  = (const float*)d_in[4];
    const float* b_f     = (const float*)d_in[5];
    const float* W_ih_b  = (const float*)d_in[6];
    const float* W_hh_b  = (const float*)d_in[7];
    const float* b_b     = (const float*)d_in[8];
    const float* h0      = (const float*)d_in[9];
    const float* c0      = (const float*)d_in[10];
    const float* W_out   = (const float*)d_in[11];
    const float* b_out   = (const float*)d_in[12];
    const float* trans   = (const float*)d_in[13];
    float* out = (float*)d_out;

    const int SMEM_LSTM = (16 * 513 * 2 + 2 * 64 * 64) * 4;  // 98,432 B
    cudaFuncSetAttribute(lstm_persistent,
                         cudaFuncAttributeMaxDynamicSharedMemorySize, SMEM_LSTM);

    prep_kernel<<<1024, 256>>>(W_ih_f, W_ih_b, h0);
    xw_gemm<<<dim3(GATES / 64, SEQ, 2), 256>>>(tokens, W_emb, b_f, b_b);
    lstm_persistent<<<NBLK, 256, SMEM_LSTM>>>(W_hh_f, W_hh_b, c0);
    feats_kernel<<<SEQ, 768>>>(W_out, b_out);
    crf_kernel<<<1, 768>>>(lengths, trans, out);
}

// round 4
// speedup vs baseline: 2.8087x; 1.0916x over previous
#include <cuda_runtime.h>
#include <math.h>

#define SEQ   512
#define BATCH 64
#define EMB   300
#define HID   512
#define GATES 2048   // 4*HID
#define NTAG  12
#define NEGV  (-10000.0f)
#define START_TAG 10
#define STOP_TAG  11
#define NBLK  128

// ---------------- scratch (device globals; no allocation) ----------------
__device__ float g_xw[2][SEQ][GATES][BATCH];   // pre-activations x@W_ih.T+b
__device__ float g_hf[SEQ][HID][BATCH];        // forward hidden states [s][u][b]
__device__ float g_hb[SEQ][HID][BATCH];        // backward hidden states in SCAN order
__device__ float g_hinit[2][HID][BATCH];       // transposed h0
__device__ float g_Wt_ih[2][EMB][GATES];       // W_ih transposed [e][j]
__device__ float g_Wout_t[2 * HID][NTAG];      // W_out transposed [k][t]
__device__ float g_feats[SEQ][BATCH][NTAG];
__device__ float g_crf_part[8];
__device__ unsigned g_cnt = 0;
__device__ volatile unsigned g_gen = 0;

// ---------------- f32x2 helpers ----------------
__device__ __forceinline__ unsigned long long splat2(float x) {
    unsigned long long r; unsigned u = __float_as_uint(x);
    asm("mov.b64 %0, {%1, %1};" : "=l"(r) : "r"(u));
    return r;
}
__device__ __forceinline__ void ffma2(unsigned long long& d,
                                      unsigned long long a,
                                      unsigned long long b) {
    asm("fma.rn.f32x2 %0, %1, %2, %0;" : "+l"(d) : "l"(a), "l"(b));
}
__device__ __forceinline__ float2 unpack2(unsigned long long v) {
    unsigned lo, hi;
    asm("mov.b64 {%0, %1}, %2;" : "=r"(lo), "=r"(hi) : "l"(v));
    float2 f; f.x = __uint_as_float(lo); f.y = __uint_as_float(hi);
    return f;
}
__device__ __forceinline__ float sigf(float x) { return 1.f / (1.f + __expf(-x)); }
__device__ __forceinline__ float tanhfast(float x) { return 2.f / (1.f + __expf(-2.f * x)) - 1.f; }

// ---------------- prep: W_ih transpose + h0 transpose + W_out transpose ----------------
__global__ void prep_kernel(const float* Wif, const float* Wib, const float* h0,
                            const float* Wout) {
    const int N_IH = 2 * EMB * GATES;
    const int N_H  = 2 * HID * BATCH;
    const int N_WO = NTAG * 2 * HID;
    const int total = N_IH + N_H + N_WO;
    for (int idx = blockIdx.x * blockDim.x + threadIdx.x; idx < total;
         idx += gridDim.x * blockDim.x) {
        int i = idx;
        if (i < N_IH) {
            int d = i / (EMB * GATES);
            int r = i % (EMB * GATES);
            int e = r / GATES, j = r % GATES;
            const float* W = d ? Wib : Wif;
            g_Wt_ih[d][e][j] = W[j * EMB + e];
        } else if ((i -= N_IH) < N_H) {
            int d = i / (HID * BATCH);
            int r = i % (HID * BATCH);
            int u = r / BATCH, b = r % BATCH;
            g_hinit[d][u][b] = h0[(d * BATCH + b) * HID + u];
        } else {
            i -= N_H;
            int k = i / NTAG, t = i % NTAG;
            g_Wout_t[k][t] = Wout[t * (2 * HID) + k];
        }
    }
}

// ---------------- input GEMM (f32x2): g_xw[dir][s][j][b] = emb(tok).W_ih[j] + bias ----------------
// Block = one s x 128 gate cols x 64 batch. 256 thr; thread = 4 cols x 8 batch (16 FFMA2 accs).
__global__ __launch_bounds__(256)
void xw_gemm(const int* __restrict__ tokens,
             const float* __restrict__ W_emb,
             const float* __restrict__ b_f,
             const float* __restrict__ b_b) {
    int dir = blockIdx.z;
    int s   = blockIdx.y;
    int n0  = blockIdx.x * 128;
    __shared__ float As[16][64];
    __shared__ float Bs[16][128];
    __shared__ int   tokS[64];
    int tid = threadIdx.x;
    if (tid < 64) {
        int srow = dir ? (SEQ - 1 - s) : s;
        tokS[tid] = tokens[tid * SEQ + srow];
    }
    __syncthreads();
    int c0 = (tid >> 3) * 4;        // col base 0..124
    int b0 = (tid & 7) * 8;         // batch base 0..56
    unsigned long long acc[4][4] = {};
    for (int k0 = 0; k0 < 304; k0 += 16) {
        // stage As [16 k][64 b]: one float4 of k per thread
        {
            int b = tid & 63, kk4 = (tid >> 6) * 4;
            int k = k0 + kk4;
            float4 v = {0.f, 0.f, 0.f, 0.f};
            if (k + 3 < EMB)
                v = *(const float4*)(W_emb + (size_t)tokS[b] * EMB + k);
            As[kk4 + 0][b] = v.x;
            As[kk4 + 1][b] = v.y;
            As[kk4 + 2][b] = v.z;
            As[kk4 + 3][b] = v.w;
        }
        // stage Bs [16 k][128 cols]: 2 float4 per thread
#pragma unroll
        for (int r = 0; r < 2; r++) {
            int idx = tid + 256 * r;
            int kk = idx >> 5, cg = idx & 31;
            float4 w = {0.f, 0.f, 0.f, 0.f};
            if (k0 + kk < EMB)
                w = *(const float4*)&g_Wt_ih[dir][k0 + kk][n0 + cg * 4];
            *(float4*)&Bs[kk][cg * 4] = w;
        }
        __syncthreads();
#pragma unroll
        for (int kk = 0; kk < 16; kk++) {
            float4 wv = *(const float4*)&Bs[kk][c0];
            unsigned long long w0 = splat2(wv.x), w1 = splat2(wv.y);
            unsigned long long w2 = splat2(wv.z), w3 = splat2(wv.w);
            ulonglong2 xA = *(const ulonglong2*)&As[kk][b0];
            ulonglong2 xB = *(const ulonglong2*)&As[kk][b0 + 4];
            ffma2(acc[0][0], xA.x, w0); ffma2(acc[0][1], xA.y, w0);
            ffma2(acc[0][2], xB.x, w0); ffma2(acc[0][3], xB.y, w0);
            ffma2(acc[1][0], xA.x, w1); ffma2(acc[1][1], xA.y, w1);
            ffma2(acc[1][2], xB.x, w1); ffma2(acc[1][3], xB.y, w1);
            ffma2(acc[2][0], xA.x, w2); ffma2(acc[2][1], xA.y, w2);
            ffma2(acc[2][2], xB.x, w2); ffma2(acc[2][3], xB.y, w2);
            ffma2(acc[3][0], xA.x, w3); ffma2(acc[3][1], xA.y, w3);
            ffma2(acc[3][2], xB.x, w3); ffma2(acc[3][3], xB.y, w3);
        }
        __syncthreads();
    }
    const float* bias = dir ? b_b : b_f;
#pragma unroll
    for (int cc = 0; cc < 4; cc++) {
        int j = n0 + c0 + cc;
        float bv = bias[j];
        float2 p0 = unpack2(acc[cc][0]), p1 = unpack2(acc[cc][1]);
        float2 p2 = unpack2(acc[cc][2]), p3 = unpack2(acc[cc][3]);
        float4 o0 = {p0.x + bv, p0.y + bv, p1.x + bv, p1.y + bv};
        float4 o1 = {p2.x + bv, p2.y + bv, p3.x + bv, p3.y + bv};
        *(float4*)&g_xw[dir][s][j][b0] = o0;
        *(float4*)&g_xw[dir][s][j][b0 + 4] = o1;
    }
}

// ---------------- persistent fused BiLSTM: 512 steps, grid-wide barrier ----------------
__global__ __launch_bounds__(256, 1)
void lstm_persistent(const float* __restrict__ Whf, const float* __restrict__ Whb,
                     const float* __restrict__ c0in) {
    extern __shared__ float smem[];
    float2* sW = (float2*)smem;                // [16 col-pairs][513 k]
    float*  sH = smem + 16 * 513 * 2;          // two 64x64 h chunks
    float*  sG = sH;                           // gate exchange aliases buffer 0
    __shared__ unsigned sgen;

    int tid = threadIdx.x;
    int bid = blockIdx.x;
    int dir = bid >> 6;
    int u0  = (bid & 63) * 8;
    const float* Whh = dir ? Whb : Whf;

    if (tid == 0) sgen = g_gen;

    for (int l = tid; l < 16 * 512; l += 256) {
        int cp = l >> 9, k = l & 511;
        int ca = cp * 2, cb = ca + 1;
        int ja = (ca >> 3) * HID + u0 + (ca & 7);
        int jb = (cb >> 3) * HID + u0 + (cb & 7);
        float2 v;
        v.x = Whh[ja * HID + k];
        v.y = Whh[jb * HID + k];
        sW[cp * 513 + k] = v;
    }

    int cp  = (tid >> 3) & 15;
    int c0i = cp * 2;
    int b0  = (tid & 7) * 4 + (tid >> 7) * 32;

    float cst[2];
#pragma unroll
    for (int idx = 0; idx < 2; idx++) {
        int p = tid + 256 * idx;
        int uu = p >> 6, b = p & 63;
        cst[idx] = c0in[(dir * BATCH + b) * HID + (u0 + uu)];
    }
    __syncthreads();

    const float2* wrow = sW + cp * 513;

    for (int s = 0; s < SEQ; s++) {
        const float* hprev = (s == 0) ? &g_hinit[dir][0][0]
                                      : (dir ? &g_hb[s - 1][0][0] : &g_hf[s - 1][0][0]);
#pragma unroll
        for (int r = 0; r < 4; r++) {
            int m = tid + 256 * r;
            float4 v = *(const float4*)(hprev + (m >> 4) * BATCH + (m & 15) * 4);
            *(float4*)(sH + (m >> 4) * BATCH + (m & 15) * 4) = v;
        }
        __syncthreads();

        unsigned long long a00 = 0, a01 = 0, a10 = 0, a11 = 0;
        int buf = 0;
#pragma unroll 1
        for (int ch = 0; ch < 8; ch++) {
            float4 pf[4];
            if (ch < 7) {
#pragma unroll
                for (int r = 0; r < 4; r++) {
                    int m = tid + 256 * r;
                    pf[r] = *(const float4*)(hprev + ((ch + 1) * 64 + (m >> 4)) * BATCH + (m & 15) * 4);
                }
            }
            const float* hb_ = sH + buf * 4096;
            int k0 = ch * 64;
#pragma unroll 8
            for (int kk = 0; kk < 64; kk += 2) {
                float2 wA = wrow[k0 + kk];
                float2 wB = wrow[k0 + kk + 1];
                ulonglong2 hA = *(const ulonglong2*)(hb_ + kk * BATCH + b0);
                ulonglong2 hB = *(const ulonglong2*)(hb_ + (kk + 1) * BATCH + b0);
                unsigned long long wa0 = splat2(wA.x), wa1 = splat2(wA.y);
                unsigned long long wb0 = splat2(wB.x), wb1 = splat2(wB.y);
                ffma2(a00, hA.x, wa0); ffma2(a01, hA.y, wa0);
                ffma2(a10, hA.x, wa1); ffma2(a11, hA.y, wa1);
                ffma2(a00, hB.x, wb0); ffma2(a01, hB.y, wb0);
                ffma2(a10, hB.x, wb1); ffma2(a11, hB.y, wb1);
            }
            if (ch < 7) {
#pragma unroll
                for (int r = 0; r < 4; r++) {
                    int m = tid + 256 * r;
                    *(float4*)(sH + (buf ^ 1) * 4096 + (m >> 4) * BATCH + (m & 15) * 4) = pf[r];
                }
            }
            __syncthreads();
            buf ^= 1;
        }

        {
            int g0 = c0i >> 3, uu0 = c0i & 7;
            int j0 = g0 * HID + u0 + uu0;
            int c1i = c0i + 1;
            int g1 = c1i >> 3, uu1 = c1i & 7;
            int j1 = g1 * HID + u0 + uu1;
            float4 x0 = *(const float4*)&g_xw[dir][s][j0][b0];
            float4 x1 = *(const float4*)&g_xw[dir][s][j1][b0];
            float2 v00 = unpack2(a00), v01 = unpack2(a01);
            float2 v10 = unpack2(a10), v11 = unpack2(a11);
            float4 o0 = {v00.x + x0.x, v00.y + x0.y, v01.x + x0.z, v01.y + x0.w};
            float4 o1 = {v10.x + x1.x, v10.y + x1.y, v11.x + x1.z, v11.y + x1.w};
            *(float4*)(sG + c0i * 68 + b0) = o0;
            *(float4*)(sG + c1i * 68 + b0) = o1;
        }
        __syncthreads();

        float* hout = dir ? &g_hb[s][0][0] : &g_hf[s][0][0];
#pragma unroll
        for (int idx = 0; idx < 2; idx++) {
            int p = tid + 256 * idx;
            int uu = p >> 6, b = p & 63;
            float gi = sG[uu * 68 + b];
            float gf = sG[(8 + uu) * 68 + b];
            float gg = sG[(16 + uu) * 68 + b];
            float go = sG[(24 + uu) * 68 + b];
            float iv = sigf(gi), fv = sigf(gf), ov = sigf(go);
            float c = fv * cst[idx] + iv * tanhfast(gg);
            cst[idx] = c;
            hout[(u0 + uu) * BATCH + b] = ov * tanhfast(c);
        }

        __syncthreads();
        if (tid == 0) {
            unsigned target = sgen + 1;
            __threadfence();
            unsigned a = atomicAdd(&g_cnt, 1);
            if (a == NBLK - 1) {
                g_cnt = 0;
                __threadfence();
                g_gen = target;
            } else {
                while (g_gen != target) { }
            }
            sgen = target;
        }
        __syncthreads();
    }
}

// ---------------- feats: K-split, 12 independent chains per thread ----------------
__global__ __launch_bounds__(256)
void feats_kernel(const float* __restrict__ b_out) {
    int s = blockIdx.x;
    int tid = threadIdx.x;
    int b = tid & 63;
    int slice = tid >> 6;               // 0..3, 256 k each over concat(hf,hb)
    __shared__ float sred[256][NTAG];
    float a[NTAG];
#pragma unroll
    for (int t = 0; t < NTAG; t++) a[t] = 0.f;

    int base = slice * 256;
    const float* hbase = (base < HID) ? &g_hf[s][base][0]
                                      : &g_hb[SEQ - 1 - s][base - HID][0];
#pragma unroll 4
    for (int k = 0; k < 256; k++) {
        float h = hbase[k * BATCH + b];
        int kg = base + k;
        float4 w0 = *(const float4*)&g_Wout_t[kg][0];
        float4 w1 = *(const float4*)&g_Wout_t[kg][4];
        float4 w2 = *(const float4*)&g_Wout_t[kg][8];
        a[0] += h * w0.x;  a[1] += h * w0.y;  a[2]  += h * w0.z;  a[3]  += h * w0.w;
        a[4] += h * w1.x;  a[5] += h * w1.y;  a[6]  += h * w1.z;  a[7]  += h * w1.w;
        a[8] += h * w2.x;  a[9] += h * w2.y;  a[10] += h * w2.z;  a[11] += h * w2.w;
    }
#pragma unroll
    for (int t = 0; t < NTAG; t++) sred[tid][t] = a[t];
    __syncthreads();
    if (tid < 64) {
#pragma unroll
        for (int t = 0; t < NTAG; t++) {
            float v = b_out[t] + sred[tid][t] + sred[64 + tid][t]
                    + sred[128 + tid][t] + sred[192 + tid][t];
            g_feats[s][tid][t] = v;
        }
    }
}

// ---------------- CRF forward: 8 blocks x 8 batches, feats prefetch ----------------
__global__ __launch_bounds__(96)
void crf_kernel(const int* __restrict__ lengths,
                const float* __restrict__ trans) {
    __shared__ float alpha[8][NTAG];
    __shared__ float tr[NTAG][NTAG];
    __shared__ float termS[8][NTAG];
    int tid = threadIdx.x;            // 96 = 8*12
    int b = tid / NTAG, t = tid % NTAG;
    int bg = blockIdx.x * 8 + b;
    for (int l = tid; l < NTAG * NTAG; l += 96)
        tr[l / NTAG][l % NTAG] = trans[l];
    alpha[b][t] = (t == START_TAG) ? 0.f : NEGV;
    int len = lengths[bg];
    __syncthreads();
    float fcur = g_feats[0][bg][t];
    for (int s = 0; s < SEQ; s++) {
        float fnext = (s + 1 < SEQ) ? g_feats[s + 1][bg][t] : 0.f;
        float v[NTAG];
        float mx = -1e30f;
#pragma unroll
        for (int p = 0; p < NTAG; p++) {
            v[p] = alpha[b][p] + tr[t][p];
            mx = fmaxf(mx, v[p]);
        }
        float sum = 0.f;
#pragma unroll
        for (int p = 0; p < NTAG; p++) sum += __expf(v[p] - mx);
        float newv = mx + __logf(sum) + fcur;
        float keep = alpha[b][t];
        float nv = (s < len) ? newv : keep;
        __syncthreads();
        alpha[b][t] = nv;
        __syncthreads();
        fcur = fnext;
    }
    termS[b][t] = alpha[b][t] + tr[STOP_TAG][t];
    __syncthreads();
    if (t == 0) {
        float mx = -1e30f;
#pragma unroll
        for (int p = 0; p < NTAG; p++) mx = fmaxf(mx, termS[b][p]);
        float sum = 0.f;
#pragma unroll
        for (int p = 0; p < NTAG; p++) sum += __expf(termS[b][p] - mx);
        if (b == tid / NTAG) {
            // one writer per batch row: accumulate block partial in shared then write
        }
        termS[b][0] = mx + __logf(sum);   // reuse termS col0 as per-b result
    }
    __syncthreads();
    if (tid == 0) {
        float s2 = 0.f;
        for (int i = 0; i < 8; i++) s2 += termS[i][0];
        g_crf_part[blockIdx.x] = s2;
    }
}

__global__ void crf_finish(float* __restrict__ out) {
    float s = 0.f;
    for (int i = 0; i < 8; i++) s += g_crf_part[i];
    out[0] = s / (float)BATCH;
}

// ---------------- launch ----------------
extern "C" void kernel_launch(void* const* d_in, const int* in_sizes, int n_in,
                              void* d_out, int out_size) {
    const int*   tokens  = (const int*)  d_in[0];
    const int*   lengths = (const int*)  d_in[1];
    const float* W_emb   = (const float*)d_in[2];
    const float* W_ih_f  = (const float*)d_in[3];
    const float* W_hh_f  = (const float*)d_in[4];
    const float* b_f     = (const float*)d_in[5];
    const float* W_ih_b  = (const float*)d_in[6];
    const float* W_hh_b  = (const float*)d_in[7];
    const float* b_b     = (const float*)d_in[8];
    const float* h0      = (const float*)d_in[9];
    const float* c0      = (const float*)d_in[10];
    const float* W_out   = (const float*)d_in[11];
    const float* b_out   = (const float*)d_in[12];
    const float* trans   = (const float*)d_in[13];
    float* out = (float*)d_out;

    const int SMEM_LSTM = (16 * 513 * 2 + 2 * 64 * 64) * 4;  // 98,432 B
    cudaFuncSetAttribute(lstm_persistent,
                         cudaFuncAttributeMaxDynamicSharedMemorySize, SMEM_LSTM);

    prep_kernel<<<1024, 256>>>(W_ih_f, W_ih_b, h0, W_out);
    xw_gemm<<<dim3(GATES / 128, SEQ, 2), 256>>>(tokens, W_emb, b_f, b_b);
    lstm_persistent<<<NBLK, 256, SMEM_LSTM>>>(W_hh_f, W_hh_b, c0);
    feats_kernel<<<SEQ, 256>>>(b_out);
    crf_kernel<<<8, 96>>>(lengths, trans);
    crf_finish<<<1, 1>>>(out);
}